// round 15
// baseline (speedup 1.0000x reference)
#include <cuda_runtime.h>

// Shapes (fixed by reference):
//   article: [256, 2048, 300] f32  (d_in[0])
//   options: [256,   64, 300] f32  (d_in[1])
//   out:     [256, 600]       f32  = concat(mean(article,1), mean(options,1))
//
// HBM-bound streaming reduction. Measured ceiling on this GB300 for this
// pattern is ~6.7 TB/s; mandatory ~650 MB of reads => ~98 us floor. This
// kernel sits at that floor (DRAM 85%, all compute pipes idle).

#define BATCH 256
#define WA    2048
#define WO    64
#define DIM   300
#define NV4   (DIM / 4)         // 75 float4 per feature row
#define SPLIT 16
#define CHUNK (WA / SPLIT)      // 128 words per article partial block
#define CHUNK_F4 (CHUNK * NV4)  // 9600 float4 per chunk
#define OPT_F4   (WO * NV4)     // 4800 float4 per options batch
#define NTHREADS 300

// Deterministic scratch (4.9 MB, L2-resident) + per-batch arrival counters
// (zero-init, reset by the last block each call -> graph-replay safe,
// no allocations, no float atomics -> bitwise-deterministic output).
__device__ float4 g_scratch[BATCH * SPLIT * NV4];
__device__ int    g_count[BATCH];

// Arrival bump with release semantics (folds the pre-arrival __threadfence
// into the atomic: this block's scratch store is ordered-before any acquirer).
__device__ __forceinline__ int arrive_release(int* counter) {
    int old;
    asm volatile("atom.release.gpu.global.add.s32 %0, [%1], 1;"
                 : "=r"(old) : "l"(counter) : "memory");
    return old;
}

__device__ __forceinline__ void fence_acquire_gpu() {
    asm volatile("fence.acquire.gpu;" ::: "memory");
}

// Single fused kernel: grid (BATCH, 1 + SPLIT), block 300 linear threads.
//  cy == 0:      full options mean -> out[b, 300:600] (scheduled FIRST so the
//                launch tail is uniform article blocks)
//  cy in [1,16]: article chunk partial -> scratch; last arrival reduces.
// Flat access: thread tid reads j = i*300 + tid; 300 % 75 == 0 so tid always
// owns feature float4 column tid%75 (register accumulation), and every warp
// request is 32B sector-aligned (no row-pitch misalignment waste).
__global__ void __launch_bounds__(NTHREADS)
fused_kernel(const float* __restrict__ art, const float* __restrict__ opt,
             float* __restrict__ out) {
    const int b   = blockIdx.x;
    const int cy  = blockIdx.y;
    const int tid = threadIdx.x;        // 0..299
    const int col = tid % NV4;          // 0..74  feature float4 column
    const int ph  = tid / NV4;          // 0..3   phase

    __shared__ float4 red[4][NV4];
    __shared__ int is_last;

    if (cy > 0) {
        const int c = cy - 1;
        const float4* __restrict__ p = reinterpret_cast<const float4*>(
            art + ((size_t)b * WA + (size_t)c * CHUNK) * DIM);

        float4 s = make_float4(0.f, 0.f, 0.f, 0.f);
#pragma unroll 16
        for (int i = 0; i < CHUNK_F4 / NTHREADS; ++i) {   // 32 iters
            float4 v = __ldcs(p + i * NTHREADS + tid);
            s.x += v.x; s.y += v.y; s.z += v.z; s.w += v.w;
        }
        red[ph][col] = s;
        __syncthreads();
        if (ph == 0) {
            float4 a = red[0][col], b4 = red[1][col], c4 = red[2][col], d4 = red[3][col];
            s.x = a.x + b4.x + c4.x + d4.x;
            s.y = a.y + b4.y + c4.y + d4.y;
            s.z = a.z + b4.z + c4.z + d4.z;
            s.w = a.w + b4.w + c4.w + d4.w;
            g_scratch[((size_t)b * SPLIT + c) * NV4 + col] = s;
        }
        __syncthreads();
        if (tid == 0) {
            // release-atomic orders this block's scratch store before the bump
            int old = arrive_release(&g_count[b]);
            is_last = (old == SPLIT - 1);
        }
        __syncthreads();

        if (is_last) {
            fence_acquire_gpu();   // observe all 16 partials
            float4 t = make_float4(0.f, 0.f, 0.f, 0.f);
#pragma unroll
            for (int k = ph; k < SPLIT; k += 4) {   // fixed order -> deterministic
                float4 v = g_scratch[((size_t)b * SPLIT + k) * NV4 + col];
                t.x += v.x; t.y += v.y; t.z += v.z; t.w += v.w;
            }
            red[ph][col] = t;
            __syncthreads();
            if (ph == 0) {
                float4 a = red[0][col], b4 = red[1][col], c4 = red[2][col], d4 = red[3][col];
                const float inv = 1.0f / (float)WA;
                t.x = (a.x + b4.x + c4.x + d4.x) * inv;
                t.y = (a.y + b4.y + c4.y + d4.y) * inv;
                t.z = (a.z + b4.z + c4.z + d4.z) * inv;
                t.w = (a.w + b4.w + c4.w + d4.w) * inv;
                reinterpret_cast<float4*>(out + (size_t)b * (2 * DIM))[col] = t;
            }
            if (tid == 0) g_count[b] = 0;   // reset for next graph replay
        }
    } else {
        // Options: 64 words, full mean, direct store. Same flat scheme.
        const float4* __restrict__ p = reinterpret_cast<const float4*>(
            opt + (size_t)b * WO * DIM);

        float4 s = make_float4(0.f, 0.f, 0.f, 0.f);
#pragma unroll 16
        for (int i = 0; i < OPT_F4 / NTHREADS; ++i) {     // 16 iters
            float4 v = __ldcs(p + i * NTHREADS + tid);
            s.x += v.x; s.y += v.y; s.z += v.z; s.w += v.w;
        }
        red[ph][col] = s;
        __syncthreads();
        if (ph == 0) {
            float4 a = red[0][col], b4 = red[1][col], c4 = red[2][col], d4 = red[3][col];
            const float inv = 1.0f / (float)WO;
            s.x = (a.x + b4.x + c4.x + d4.x) * inv;
            s.y = (a.y + b4.y + c4.y + d4.y) * inv;
            s.z = (a.z + b4.z + c4.z + d4.z) * inv;
            s.w = (a.w + b4.w + c4.w + d4.w) * inv;
            reinterpret_cast<float4*>(out + (size_t)b * (2 * DIM) + DIM)[col] = s;
        }
    }
}

extern "C" void kernel_launch(void* const* d_in, const int* in_sizes, int n_in,
                              void* d_out, int out_size) {
    const float* article = (const float*)d_in[0];
    const float* options = (const float*)d_in[1];
    float* out = (float*)d_out;

    dim3 grid(BATCH, 1 + SPLIT);   // 256 options blocks first, then 4096 article
    fused_kernel<<<grid, NTHREADS>>>(article, options, out);
}

// round 17
// speedup vs baseline: 1.0337x; 1.0337x over previous
#include <cuda_runtime.h>

// Shapes (fixed by reference):
//   article: [256, 2048, 300] f32  (d_in[0])
//   options: [256,   64, 300] f32  (d_in[1])
//   out:     [256, 600]       f32  = concat(mean(article,1), mean(options,1))
//
// HBM-bound streaming reduction. Measured ceiling on this GB300 for this
// pattern is ~6.7 TB/s; mandatory ~650 MB of reads => ~98 us floor. This
// kernel sits at that floor (DRAM ~85%, all compute pipes idle). R16 adds
// discard.global.L2 on consumed scratch lines to kill their dead writeback.

#define BATCH 256
#define WA    2048
#define WO    64
#define DIM   300
#define NV4   (DIM / 4)         // 75 float4 per feature row
#define SPLIT 16
#define CHUNK (WA / SPLIT)      // 128 words per article partial block
#define CHUNK_F4 (CHUNK * NV4)  // 9600 float4 per chunk
#define OPT_F4   (WO * NV4)     // 4800 float4 per options batch
#define NTHREADS 300

// Scratch region per batch: SPLIT * NV4 * 16 = 19200 bytes (150 x 128B lines,
// 128B-aligned because base is 128-aligned and 19200 % 128 == 0).
#define BATCH_SCRATCH_BYTES (SPLIT * NV4 * 16)
#define BATCH_SCRATCH_LINES (BATCH_SCRATCH_BYTES / 128)   // 150

// Deterministic scratch (4.9 MB, L2-resident) + per-batch arrival counters
// (zero-init, reset by the last block each call -> graph-replay safe,
// no allocations, no float atomics -> bitwise-deterministic output).
__device__ __align__(128) float4 g_scratch[BATCH * SPLIT * NV4];
__device__ int g_count[BATCH];

// Arrival bump with release semantics (folds the pre-arrival __threadfence
// into the atomic: this block's scratch store is ordered-before any acquirer).
__device__ __forceinline__ int arrive_release(int* counter) {
    int old;
    asm volatile("atom.release.gpu.global.add.s32 %0, [%1], 1;"
                 : "=r"(old) : "l"(counter) : "memory");
    return old;
}

__device__ __forceinline__ void fence_acquire_gpu() {
    asm volatile("fence.acquire.gpu;" ::: "memory");
}

// Drop a dirty 128B L2 line without writing it back to DRAM. The data is
// dead (already consumed); it is fully rewritten on the next launch before
// any read, so graph replay stays correct.
__device__ __forceinline__ void discard_l2_line(const void* p) {
    asm volatile("discard.global.L2 [%0], 128;" :: "l"(p) : "memory");
}

// Single fused kernel: grid (BATCH, 1 + SPLIT), block 300 linear threads.
//  cy == 0:      full options mean -> out[b, 300:600] (scheduled FIRST so the
//                launch tail is uniform article blocks)
//  cy in [1,16]: article chunk partial -> scratch; last arrival reduces.
// Flat access: thread tid reads j = i*300 + tid; 300 % 75 == 0 so tid always
// owns feature float4 column tid%75 (register accumulation), and every warp
// request is 32B sector-aligned (no row-pitch misalignment waste).
__global__ void __launch_bounds__(NTHREADS)
fused_kernel(const float* __restrict__ art, const float* __restrict__ opt,
             float* __restrict__ out) {
    const int b   = blockIdx.x;
    const int cy  = blockIdx.y;
    const int tid = threadIdx.x;        // 0..299
    const int col = tid % NV4;          // 0..74  feature float4 column
    const int ph  = tid / NV4;          // 0..3   phase

    __shared__ float4 red[4][NV4];
    __shared__ int is_last;

    if (cy > 0) {
        const int c = cy - 1;
        const float4* __restrict__ p = reinterpret_cast<const float4*>(
            art + ((size_t)b * WA + (size_t)c * CHUNK) * DIM);

        float4 s = make_float4(0.f, 0.f, 0.f, 0.f);
#pragma unroll 16
        for (int i = 0; i < CHUNK_F4 / NTHREADS; ++i) {   // 32 iters
            float4 v = __ldcs(p + i * NTHREADS + tid);
            s.x += v.x; s.y += v.y; s.z += v.z; s.w += v.w;
        }
        red[ph][col] = s;
        __syncthreads();
        if (ph == 0) {
            float4 a = red[0][col], b4 = red[1][col], c4 = red[2][col], d4 = red[3][col];
            s.x = a.x + b4.x + c4.x + d4.x;
            s.y = a.y + b4.y + c4.y + d4.y;
            s.z = a.z + b4.z + c4.z + d4.z;
            s.w = a.w + b4.w + c4.w + d4.w;
            g_scratch[((size_t)b * SPLIT + c) * NV4 + col] = s;
        }
        __syncthreads();
        if (tid == 0) {
            // release-atomic orders this block's scratch store before the bump
            int old = arrive_release(&g_count[b]);
            is_last = (old == SPLIT - 1);
        }
        __syncthreads();

        if (is_last) {
            fence_acquire_gpu();   // observe all 16 partials
            float4 t = make_float4(0.f, 0.f, 0.f, 0.f);
#pragma unroll
            for (int k = ph; k < SPLIT; k += 4) {   // fixed order -> deterministic
                float4 v = g_scratch[((size_t)b * SPLIT + k) * NV4 + col];
                t.x += v.x; t.y += v.y; t.z += v.z; t.w += v.w;
            }
            red[ph][col] = t;
            __syncthreads();

            // All partials for batch b are consumed (held in red[][]). Drop
            // the dirty scratch lines so they never write back to DRAM.
            if (tid < BATCH_SCRATCH_LINES) {
                const char* base = reinterpret_cast<const char*>(
                    &g_scratch[(size_t)b * SPLIT * NV4]);
                discard_l2_line(base + tid * 128);
            }

            if (ph == 0) {
                float4 a = red[0][col], b4 = red[1][col], c4 = red[2][col], d4 = red[3][col];
                const float inv = 1.0f / (float)WA;
                t.x = (a.x + b4.x + c4.x + d4.x) * inv;
                t.y = (a.y + b4.y + c4.y + d4.y) * inv;
                t.z = (a.z + b4.z + c4.z + d4.z) * inv;
                t.w = (a.w + b4.w + c4.w + d4.w) * inv;
                reinterpret_cast<float4*>(out + (size_t)b * (2 * DIM))[col] = t;
            }
            if (tid == 0) g_count[b] = 0;   // reset for next graph replay
        }
    } else {
        // Options: 64 words, full mean, direct store. Same flat scheme.
        const float4* __restrict__ p = reinterpret_cast<const float4*>(
            opt + (size_t)b * WO * DIM);

        float4 s = make_float4(0.f, 0.f, 0.f, 0.f);
#pragma unroll 16
        for (int i = 0; i < OPT_F4 / NTHREADS; ++i) {     // 16 iters
            float4 v = __ldcs(p + i * NTHREADS + tid);
            s.x += v.x; s.y += v.y; s.z += v.z; s.w += v.w;
        }
        red[ph][col] = s;
        __syncthreads();
        if (ph == 0) {
            float4 a = red[0][col], b4 = red[1][col], c4 = red[2][col], d4 = red[3][col];
            const float inv = 1.0f / (float)WO;
            s.x = (a.x + b4.x + c4.x + d4.x) * inv;
            s.y = (a.y + b4.y + c4.y + d4.y) * inv;
            s.z = (a.z + b4.z + c4.z + d4.z) * inv;
            s.w = (a.w + b4.w + c4.w + d4.w) * inv;
            reinterpret_cast<float4*>(out + (size_t)b * (2 * DIM) + DIM)[col] = s;
        }
    }
}

extern "C" void kernel_launch(void* const* d_in, const int* in_sizes, int n_in,
                              void* d_out, int out_size) {
    const float* article = (const float*)d_in[0];
    const float* options = (const float*)d_in[1];
    float* out = (float*)d_out;

    dim3 grid(BATCH, 1 + SPLIT);   // 256 options blocks first, then 4096 article
    fused_kernel<<<grid, NTHREADS>>>(article, options, out);
}